// round 13
// baseline (speedup 1.0000x reference)
#include <cuda_runtime.h>
#include <cuda_fp16.h>

// Non-local means, 4 x 1 x 1024 x 1024 fp32.
// h = 7/255, template 7x7, search 21x21, reflect-101 padding.
//
// SMEM tiles indexed by unreflected global coords (halo 13):
//   Sf : fp32 reflect-padded values (tail/epilogue exactness)
//   S4 : uint2 quads S4[j] = (half2(x[j],x[j+1]), half2(x[j+2],x[j+3]))
//        -> one LDS.64 per template row serves FOUR search offsets
//        (dx..dx+3) as two independent half2 pipelines (double ILP).
// Vertical 7-box via PREFIX-SUM RING: P_m = running sum of diff^2 (one
// HFMA2/row), window V = P_m - P_{m-7} (ring slot = SSA register).
// Early rejection (4-row quads, one ballot covers all 4 dx): non-negligible
// weight needs ALL 7 window lanes V <= TH; ballot the quad min, test a
// 7-consecutive-bit run; no run -> all weights in quad < 2^-25 -> skip
// shuffle/ex2/accumulate tail. Error bound 441 * 2^-25 ~ 1.3e-5
// (reference fp32 exp underflows these weights to 0 anyway).
//
// R12: R9 structure (per-row LDS, proven 588us) + LDS.64 quad packing
// (halve MIO ops, two independent prefix chains hide HFMA2/LDS latency)
// + halved ballot count. R10's register-cache approach is reverted (it
// traded issueable width for stalls).

static constexpr int IMG_H = 1024;
static constexpr int IMG_W = 1024;
static constexpr int OUT_H = 32;
static constexpr int OUT_W = 104;          // 4 warps * 26
static constexpr int REG_H = OUT_H + 26;   // 58
static constexpr int REG_W = OUT_W + 26;   // 130
static constexpr int NTHREADS = 256;
static constexpr int TILE_N = REG_H * REG_W;            // 7540
static constexpr int SMEM_BYTES = TILE_N * 4 + TILE_N * 8;  // Sf + S4

// dist/h^2 = S49 * 65025/2401 = K*S49 ; weight = 2^(-C2*S49), C2 = K*log2e
static constexpr float C2F = 39.07174f;
// skip-safe: s7raw > 25/C2 = 0.6399 -> w < 2^-25. Margin for half rounding.
static constexpr float THR = 0.66f;

__device__ __forceinline__ int refl(int g, int n) {
    g = (g < 0) ? -g : g;
    return (g >= n) ? (2 * n - 2 - g) : g;
}

__device__ __forceinline__ float ex2(float x) {
    float r;
    asm("ex2.approx.ftz.f32 %0, %1;" : "=f"(r) : "f"(x));
    return r;
}

__device__ __forceinline__ __half2 u2lo(const uint2& v) {
    return *reinterpret_cast<const __half2*>(&v.x);
}
__device__ __forceinline__ __half2 u2hi(const uint2& v) {
    return *reinterpret_cast<const __half2*>(&v.y);
}

// Accumulate the tail for one half2 pipeline (2 dx columns).
// HI: accumulate the hi component too.
template <bool HI>
__device__ __forceinline__ void tail_pair(
    const __half2 (&Vq)[4], const float* __restrict__ Fp, int i0,
    float (&wacc)[16], float (&vacc)[16])
{
    #pragma unroll
    for (int s = 0; s < 4; ++s) {
        __half2 h = Vq[s];
        __half2 a = __hadd2(h, __shfl_down_sync(0xffffffffu, h, 1));
        __half2 b2 = __hadd2(a, __shfl_down_sync(0xffffffffu, a, 2));
        __half2 s7 = __hadd2(b2,
                     __hadd2(__shfl_down_sync(0xffffffffu, a, 4),
                             __shfl_down_sync(0xffffffffu, h, 6)));
        int i = i0 + s;
        const float* Fr = Fp + i * REG_W;
        float wlo = ex2(-C2F * __low2float(s7));
        wacc[i] += wlo;
        vacc[i]  = fmaf(wlo, Fr[0], vacc[i]);
        if (HI) {
            float whi = ex2(-C2F * __high2float(s7));
            wacc[i] += whi;
            vacc[i]  = fmaf(whi, Fr[1], vacc[i]);
        }
    }
}

// One 4-dx group (dxe..dxe+3) at one dy; two half2 pipelines from LDS.64.
// RB  : reflect template rows (edge row-strips).
// LAST: group is the lone dx=10 column pair; only pipeline-0 lo is valid.
template <bool RB, bool LAST>
__device__ __forceinline__ void nlm_group(
    const float* __restrict__ Sf, const uint2* __restrict__ S4,
    const __half2* __restrict__ Cc2,
    float (&wacc)[16], float (&vacc)[16],
    int rw0, int r0m13, int colB, int colS, int dy, int dxe)
{
    const int cb = colB + dxe;
    const uint2* B = S4 + (dy - r0m13) * REG_W + cb;
    const uint2* Bp = B + (rw0 - 3) * REG_W;       // interior: row m const off
    const float* Fp = Sf + (rw0 + dy - r0m13) * REG_W + colS + dxe;
    const __half thr = __float2half(THR);

    __half2 ring0[7], ring1[7];
    __half2 P0 = __float2half2_rn(0.0f);
    __half2 P1 = P0;
    ring0[6] = P0; ring1[6] = P1;      // P_{-1} = 0, read at m = 6
    #pragma unroll
    for (int m = 0; m < 6; ++m) {
        uint2 bv;
        if (RB) bv = B[refl(rw0 - 3 + m, IMG_H) * REG_W];
        else    bv = Bp[m * REG_W];
        __half2 t0 = __hsub2(Cc2[m], u2lo(bv));
        P0 = __hfma2(t0, t0, P0);
        ring0[m] = P0;
        if (!LAST) {
            __half2 t1 = __hsub2(Cc2[m], u2hi(bv));
            P1 = __hfma2(t1, t1, P1);
            ring1[m] = P1;
        }
    }
    #pragma unroll
    for (int g = 0; g < 4; ++g) {
        __half2 Vq0[4], Vq1[4];
        #pragma unroll
        for (int s = 0; s < 4; ++s) {
            const int m = 4 * g + 6 + s;
            uint2 bv;
            if (RB) bv = B[refl(rw0 - 3 + m, IMG_H) * REG_W];
            else    bv = Bp[m * REG_W];
            __half2 t0 = __hsub2(Cc2[m], u2lo(bv));
            P0 = __hfma2(t0, t0, P0);
            Vq0[s] = __hsub2(P0, ring0[m % 7]);
            ring0[m % 7] = P0;
            if (!LAST) {
                __half2 t1 = __hsub2(Cc2[m], u2hi(bv));
                P1 = __hfma2(t1, t1, P1);
                Vq1[s] = __hsub2(P1, ring1[m % 7]);
                ring1[m % 7] = P1;
            }
        }
        // screen: min over the whole quad (4 rows x 4 dx; lo-only for LAST)
        __half mn;
        if (LAST) {
            __half2 m0 = __hmin2(__hmin2(Vq0[0], Vq0[1]),
                                 __hmin2(Vq0[2], Vq0[3]));
            mn = __low2half(m0);
        } else {
            __half2 m0 = __hmin2(__hmin2(Vq0[0], Vq0[1]),
                                 __hmin2(Vq0[2], Vq0[3]));
            __half2 m1 = __hmin2(__hmin2(Vq1[0], Vq1[1]),
                                 __hmin2(Vq1[2], Vq1[3]));
            __half2 mm = __hmin2(m0, m1);
            mn = __hmin(__low2half(mm), __high2half(mm));
        }
        unsigned msk = __ballot_sync(0xffffffffu, __hle(mn, thr));
        unsigned r = msk & (msk >> 1);
        r &= (r >> 2);
        r &= (r >> 3);                 // 7-consecutive-lane run
        if (r) {
            const int i0 = 4 * g;
            tail_pair<!LAST>(Vq0, Fp, i0, wacc, vacc);
            if (!LAST) tail_pair<true>(Vq1, Fp + 2, i0, wacc, vacc);
        }
    }
}

template <bool RB>
__device__ __forceinline__ void nlm_accum(
    const float* __restrict__ Sf, const uint2* __restrict__ S4,
    const __half2* __restrict__ Cc2,
    float (&wacc)[16], float (&vacc)[16],
    int rw0, int r0m13, int colB, int colS)
{
    #pragma unroll 1
    for (int grp = 0; grp < 5; ++grp) {
        const int dxe = -10 + 4 * grp;
        #pragma unroll 1
        for (int dy = -10; dy <= 10; ++dy) {
            nlm_group<RB, false>(Sf, S4, Cc2, wacc, vacc,
                                 rw0, r0m13, colB, colS, dy, dxe);
        }
    }
    #pragma unroll 1
    for (int dy = -10; dy <= 10; ++dy) {
        nlm_group<RB, true>(Sf, S4, Cc2, wacc, vacc,
                            rw0, r0m13, colB, colS, dy, 10);
    }
}

__global__ __launch_bounds__(NTHREADS, 2)
void nlm_kernel(const float* __restrict__ x, float* __restrict__ out) {
    extern __shared__ unsigned char smem_raw[];
    float* Sf = reinterpret_cast<float*>(smem_raw);
    uint2* S4 = reinterpret_cast<uint2*>(smem_raw + TILE_N * 4);

    const int b  = blockIdx.z;
    const int r0 = blockIdx.y * OUT_H;
    const int c0 = blockIdx.x * OUT_W;
    const int tid = threadIdx.x;

    // fp32 reflect-padded tile
    const float* xb = x + (size_t)b * (IMG_H * IMG_W);
    #pragma unroll 4
    for (int idx = tid; idx < TILE_N; idx += NTHREADS) {
        int i = idx / REG_W;
        int j = idx - i * REG_W;
        int gr = refl(r0 - 13 + i, IMG_H);
        int gc = refl(c0 - 13 + j, IMG_W);
        Sf[idx] = xb[gr * IMG_W + gc];
    }
    __syncthreads();

    // quad tile: S4[j] = (half2(x[j],x[j+1]), half2(x[j+2],x[j+3])),
    // indices clamped at row end (clamped entries are never consumed).
    #pragma unroll 4
    for (int idx = tid; idx < TILE_N; idx += NTHREADS) {
        int i = idx / REG_W;
        int j = idx - i * REG_W;
        const float* row = Sf + i * REG_W;
        int j1 = (j + 1 < REG_W) ? j + 1 : REG_W - 1;
        int j2 = (j + 2 < REG_W) ? j + 2 : REG_W - 1;
        int j3 = (j + 3 < REG_W) ? j + 3 : REG_W - 1;
        __half2 lo = __floats2half2_rn(row[j],  row[j1]);
        __half2 hi = __floats2half2_rn(row[j2], row[j3]);
        uint2 v;
        v.x = *reinterpret_cast<unsigned*>(&lo);
        v.y = *reinterpret_cast<unsigned*>(&hi);
        S4[idx] = v;
    }
    __syncthreads();

    const int w = tid >> 5, l = tid & 31;
    const int wx = w & 3, wy = w >> 2;
    const int rw0 = r0 + wy * 16;
    const int c0w = c0 + wx * 26;
    const int u = c0w - 3 + l;
    const int qc = refl(u, IMG_W);
    const int r0m13 = r0 - 13;
    const int c0m13 = c0 - 13;
    const int colB = qc - c0m13;
    const int lclamp = (l < 26) ? l : 25;
    const int colS = (c0w + lclamp) - c0m13;

    // center-column cache as duplicated half2
    __half2 Cc2[22];
    #pragma unroll
    for (int m = 0; m < 22; ++m) {
        int qr = refl(rw0 - 3 + m, IMG_H);
        Cc2[m] = __float2half2_rn(Sf[(qr - r0m13) * REG_W + colB]);
    }

    float wacc[16], vacc[16];
    #pragma unroll
    for (int i = 0; i < 16; ++i) { wacc[i] = 0.0f; vacc[i] = 0.0f; }

    const bool rowRefl = (rw0 - 3 < 0) || (rw0 + 18 >= IMG_H);
    if (!rowRefl) {
        nlm_accum<false>(Sf, S4, Cc2, wacc, vacc, rw0, r0m13, colB, colS);
    } else {
        nlm_accum<true>(Sf, S4, Cc2, wacc, vacc, rw0, r0m13, colB, colS);
    }

    const int cout = c0w + l;
    if (l < 26 && cout < IMG_W) {
        float* ob = out + (size_t)b * (IMG_H * IMG_W);
        #pragma unroll
        for (int i = 0; i < 16; ++i) {
            float q = vacc[i] / wacc[i];
            q = fminf(fmaxf(q, 0.0f), 1.0f);
            ob[(rw0 + i) * IMG_W + cout] = q;
        }
    }
}

extern "C" void kernel_launch(void* const* d_in, const int* in_sizes, int n_in,
                              void* d_out, int out_size) {
    const float* x = (const float*)d_in[0];
    float* out = (float*)d_out;
    (void)in_sizes; (void)n_in; (void)out_size;

    cudaFuncSetAttribute(nlm_kernel,
                         cudaFuncAttributeMaxDynamicSharedMemorySize,
                         SMEM_BYTES);

    dim3 grid((IMG_W + OUT_W - 1) / OUT_W,   // 10
              IMG_H / OUT_H,                 // 32
              4);
    dim3 block(NTHREADS);
    nlm_kernel<<<grid, block, SMEM_BYTES>>>(x, out);
}

// round 17
// speedup vs baseline: 1.6550x; 1.6550x over previous
#include <cuda_runtime.h>
#include <cuda_fp16.h>

// Non-local means, 4 x 1 x 1024 x 1024 fp32.
// h = 7/255, template 7x7, search 21x21, reflect-101 padding.
//
// SMEM tiles indexed by unreflected global coords (halo 13):
//   Sf : fp32 reflect-padded values (tail/epilogue exactness)
//   S4 : uint2 quads S4[j] = (half2(x[j],x[j+1]), half2(x[j+2],x[j+3]))
//        -> one LDS.64 per template row serves FOUR search offsets
//        (dx..dx+3) as two independent half2 pipelines (double ILP).
// Vertical 7-box via PREFIX-SUM RING: P_m = running sum of diff^2 (one
// HFMA2/row), window V = P_m - P_{m-7} (ring slot = SSA register).
// Early rejection: PER-PIPELINE 4-row quad screens (4 rows x 2 dx, the
// R9-proven granularity — R8/R12 showed widening the screened set explodes
// the trigger rate). Non-negligible weight needs ALL 7 window lanes V <= TH;
// ballot the quad min, test a 7-consecutive-bit run; no run -> all weights
// in that pipeline's quad < 2^-25 -> skip its shuffle/ex2/accumulate tail.
// Error bound 441 * 2^-25 ~ 1.3e-5 (reference fp32 exp underflows these to 0).

static constexpr int IMG_H = 1024;
static constexpr int IMG_W = 1024;
static constexpr int OUT_H = 32;
static constexpr int OUT_W = 104;          // 4 warps * 26
static constexpr int REG_H = OUT_H + 26;   // 58
static constexpr int REG_W = OUT_W + 26;   // 130
static constexpr int NTHREADS = 256;
static constexpr int TILE_N = REG_H * REG_W;            // 7540
static constexpr int SMEM_BYTES = TILE_N * 4 + TILE_N * 8;  // Sf + S4

// dist/h^2 = S49 * 65025/2401 = K*S49 ; weight = 2^(-C2*S49), C2 = K*log2e
static constexpr float C2F = 39.07174f;
// skip-safe: s7raw > 25/C2 = 0.6399 -> w < 2^-25. Margin for half rounding.
static constexpr float THR = 0.66f;

__device__ __forceinline__ int refl(int g, int n) {
    g = (g < 0) ? -g : g;
    return (g >= n) ? (2 * n - 2 - g) : g;
}

__device__ __forceinline__ float ex2(float x) {
    float r;
    asm("ex2.approx.ftz.f32 %0, %1;" : "=f"(r) : "f"(x));
    return r;
}

__device__ __forceinline__ __half2 u2lo(const uint2& v) {
    return *reinterpret_cast<const __half2*>(&v.x);
}
__device__ __forceinline__ __half2 u2hi(const uint2& v) {
    return *reinterpret_cast<const __half2*>(&v.y);
}

// Screen + tail for one half2 pipeline's quad (4 rows x 2 dx).
// HI: accumulate the hi (dx+1) component too.
template <bool HI>
__device__ __forceinline__ void screen_tail(
    const __half2 (&Vq)[4], const float* __restrict__ Fp, int i0, __half thr,
    float (&wacc)[16], float (&vacc)[16])
{
    __half2 mn2 = __hmin2(__hmin2(Vq[0], Vq[1]), __hmin2(Vq[2], Vq[3]));
    __half mn;
    if (HI) mn = __hmin(__low2half(mn2), __high2half(mn2));
    else    mn = __low2half(mn2);
    unsigned msk = __ballot_sync(0xffffffffu, __hle(mn, thr));
    unsigned r = msk & (msk >> 1);
    r &= (r >> 2);
    r &= (r >> 3);                 // 7-consecutive-lane run
    if (r) {
        #pragma unroll
        for (int s = 0; s < 4; ++s) {
            __half2 h = Vq[s];
            __half2 a = __hadd2(h, __shfl_down_sync(0xffffffffu, h, 1));
            __half2 b2 = __hadd2(a, __shfl_down_sync(0xffffffffu, a, 2));
            __half2 s7 = __hadd2(b2,
                         __hadd2(__shfl_down_sync(0xffffffffu, a, 4),
                                 __shfl_down_sync(0xffffffffu, h, 6)));
            int i = i0 + s;
            const float* Fr = Fp + i * REG_W;
            float wlo = ex2(-C2F * __low2float(s7));
            wacc[i] += wlo;
            vacc[i]  = fmaf(wlo, Fr[0], vacc[i]);
            if (HI) {
                float whi = ex2(-C2F * __high2float(s7));
                wacc[i] += whi;
                vacc[i]  = fmaf(whi, Fr[1], vacc[i]);
            }
        }
    }
}

// One 4-dx group (dxe..dxe+3) at one dy; two half2 pipelines from LDS.64,
// each with its OWN 4-row screen (R9 granularity).
// RB  : reflect template rows (edge row-strips).
// LAST: group is the lone dx=10 column; only pipeline-0 lo is valid.
template <bool RB, bool LAST>
__device__ __forceinline__ void nlm_group(
    const float* __restrict__ Sf, const uint2* __restrict__ S4,
    const __half2* __restrict__ Cc2,
    float (&wacc)[16], float (&vacc)[16],
    int rw0, int r0m13, int colB, int colS, int dy, int dxe)
{
    const int cb = colB + dxe;
    const uint2* B = S4 + (dy - r0m13) * REG_W + cb;
    const uint2* Bp = B + (rw0 - 3) * REG_W;       // interior: row m const off
    const float* Fp = Sf + (rw0 + dy - r0m13) * REG_W + colS + dxe;
    const __half thr = __float2half(THR);

    __half2 ring0[7], ring1[7];
    __half2 P0 = __float2half2_rn(0.0f);
    __half2 P1 = P0;
    ring0[6] = P0; ring1[6] = P1;      // P_{-1} = 0, read at m = 6
    #pragma unroll
    for (int m = 0; m < 6; ++m) {
        uint2 bv;
        if (RB) bv = B[refl(rw0 - 3 + m, IMG_H) * REG_W];
        else    bv = Bp[m * REG_W];
        __half2 t0 = __hsub2(Cc2[m], u2lo(bv));
        P0 = __hfma2(t0, t0, P0);
        ring0[m] = P0;
        if (!LAST) {
            __half2 t1 = __hsub2(Cc2[m], u2hi(bv));
            P1 = __hfma2(t1, t1, P1);
            ring1[m] = P1;
        }
    }
    #pragma unroll
    for (int g = 0; g < 4; ++g) {
        __half2 Vq0[4], Vq1[4];
        #pragma unroll
        for (int s = 0; s < 4; ++s) {
            const int m = 4 * g + 6 + s;
            uint2 bv;
            if (RB) bv = B[refl(rw0 - 3 + m, IMG_H) * REG_W];
            else    bv = Bp[m * REG_W];
            __half2 t0 = __hsub2(Cc2[m], u2lo(bv));
            P0 = __hfma2(t0, t0, P0);
            Vq0[s] = __hsub2(P0, ring0[m % 7]);
            ring0[m % 7] = P0;
            if (!LAST) {
                __half2 t1 = __hsub2(Cc2[m], u2hi(bv));
                P1 = __hfma2(t1, t1, P1);
                Vq1[s] = __hsub2(P1, ring1[m % 7]);
                ring1[m % 7] = P1;
            }
        }
        const int i0 = 4 * g;
        // independent screens per pipeline: trigger rate stays at the
        // proven 4-row x 2-dx granularity.
        screen_tail<!LAST>(Vq0, Fp, i0, thr, wacc, vacc);
        if (!LAST) screen_tail<true>(Vq1, Fp + 2, i0, thr, wacc, vacc);
    }
}

template <bool RB>
__device__ __forceinline__ void nlm_accum(
    const float* __restrict__ Sf, const uint2* __restrict__ S4,
    const __half2* __restrict__ Cc2,
    float (&wacc)[16], float (&vacc)[16],
    int rw0, int r0m13, int colB, int colS)
{
    #pragma unroll 1
    for (int grp = 0; grp < 5; ++grp) {
        const int dxe = -10 + 4 * grp;
        #pragma unroll 1
        for (int dy = -10; dy <= 10; ++dy) {
            nlm_group<RB, false>(Sf, S4, Cc2, wacc, vacc,
                                 rw0, r0m13, colB, colS, dy, dxe);
        }
    }
    #pragma unroll 1
    for (int dy = -10; dy <= 10; ++dy) {
        nlm_group<RB, true>(Sf, S4, Cc2, wacc, vacc,
                            rw0, r0m13, colB, colS, dy, 10);
    }
}

__global__ __launch_bounds__(NTHREADS, 2)
void nlm_kernel(const float* __restrict__ x, float* __restrict__ out) {
    extern __shared__ unsigned char smem_raw[];
    float* Sf = reinterpret_cast<float*>(smem_raw);
    uint2* S4 = reinterpret_cast<uint2*>(smem_raw + TILE_N * 4);

    const int b  = blockIdx.z;
    const int r0 = blockIdx.y * OUT_H;
    const int c0 = blockIdx.x * OUT_W;
    const int tid = threadIdx.x;

    // fp32 reflect-padded tile
    const float* xb = x + (size_t)b * (IMG_H * IMG_W);
    #pragma unroll 4
    for (int idx = tid; idx < TILE_N; idx += NTHREADS) {
        int i = idx / REG_W;
        int j = idx - i * REG_W;
        int gr = refl(r0 - 13 + i, IMG_H);
        int gc = refl(c0 - 13 + j, IMG_W);
        Sf[idx] = xb[gr * IMG_W + gc];
    }
    __syncthreads();

    // quad tile: S4[j] = (half2(x[j],x[j+1]), half2(x[j+2],x[j+3])),
    // indices clamped at row end (clamped entries are never consumed).
    #pragma unroll 4
    for (int idx = tid; idx < TILE_N; idx += NTHREADS) {
        int i = idx / REG_W;
        int j = idx - i * REG_W;
        const float* row = Sf + i * REG_W;
        int j1 = (j + 1 < REG_W) ? j + 1 : REG_W - 1;
        int j2 = (j + 2 < REG_W) ? j + 2 : REG_W - 1;
        int j3 = (j + 3 < REG_W) ? j + 3 : REG_W - 1;
        __half2 lo = __floats2half2_rn(row[j],  row[j1]);
        __half2 hi = __floats2half2_rn(row[j2], row[j3]);
        uint2 v;
        v.x = *reinterpret_cast<unsigned*>(&lo);
        v.y = *reinterpret_cast<unsigned*>(&hi);
        S4[idx] = v;
    }
    __syncthreads();

    const int w = tid >> 5, l = tid & 31;
    const int wx = w & 3, wy = w >> 2;
    const int rw0 = r0 + wy * 16;
    const int c0w = c0 + wx * 26;
    const int u = c0w - 3 + l;
    const int qc = refl(u, IMG_W);
    const int r0m13 = r0 - 13;
    const int c0m13 = c0 - 13;
    const int colB = qc - c0m13;
    const int lclamp = (l < 26) ? l : 25;
    const int colS = (c0w + lclamp) - c0m13;

    // center-column cache as duplicated half2
    __half2 Cc2[22];
    #pragma unroll
    for (int m = 0; m < 22; ++m) {
        int qr = refl(rw0 - 3 + m, IMG_H);
        Cc2[m] = __float2half2_rn(Sf[(qr - r0m13) * REG_W + colB]);
    }

    float wacc[16], vacc[16];
    #pragma unroll
    for (int i = 0; i < 16; ++i) { wacc[i] = 0.0f; vacc[i] = 0.0f; }

    const bool rowRefl = (rw0 - 3 < 0) || (rw0 + 18 >= IMG_H);
    if (!rowRefl) {
        nlm_accum<false>(Sf, S4, Cc2, wacc, vacc, rw0, r0m13, colB, colS);
    } else {
        nlm_accum<true>(Sf, S4, Cc2, wacc, vacc, rw0, r0m13, colB, colS);
    }

    const int cout = c0w + l;
    if (l < 26 && cout < IMG_W) {
        float* ob = out + (size_t)b * (IMG_H * IMG_W);
        #pragma unroll
        for (int i = 0; i < 16; ++i) {
            float q = vacc[i] / wacc[i];
            q = fminf(fmaxf(q, 0.0f), 1.0f);
            ob[(rw0 + i) * IMG_W + cout] = q;
        }
    }
}

extern "C" void kernel_launch(void* const* d_in, const int* in_sizes, int n_in,
                              void* d_out, int out_size) {
    const float* x = (const float*)d_in[0];
    float* out = (float*)d_out;
    (void)in_sizes; (void)n_in; (void)out_size;

    cudaFuncSetAttribute(nlm_kernel,
                         cudaFuncAttributeMaxDynamicSharedMemorySize,
                         SMEM_BYTES);

    dim3 grid((IMG_W + OUT_W - 1) / OUT_W,   // 10
              IMG_H / OUT_H,                 // 32
              4);
    dim3 block(NTHREADS);
    nlm_kernel<<<grid, block, SMEM_BYTES>>>(x, out);
}